// round 15
// baseline (speedup 1.0000x reference)
#include <cuda_runtime.h>
#include <cuda_fp16.h>
#include <cstdint>
#include <math.h>

#define FULL 0xffffffffu

// ===================== device globals =====================
__device__ __half g_Ure[256 * 256];        // U_re[i][k], K-major
__device__ __half g_Uim[256 * 256];        // U_im[i][k], K-major
__device__ int g_count = 0;                // barrier: 296 zero-arrivals + 256 U columns
__device__ int g_done  = 0;                // completion counter for self-reset

// ===================== scalar fused-block sim (validated R1/R6) =====================
template<int CB, int TB>
__device__ __forceinline__ void apply_block(float (&re)[8], float (&im)[8],
                                            const float* cf, unsigned lane) {
    float cs = cf[0], ss = cf[1];
    float ar = cf[2], ai = cf[3], br = cf[4], bi = cf[5];
    if constexpr (TB >= 5) {
        static_assert(CB >= 5, "in-lane target gates have in-register control");
        constexpr int tm = 1 << (TB - 5);
#pragma unroll
        for (int r0 = 0; r0 < 8; r0++) {
            if (r0 & tm) continue;
            const int r1 = r0 | tm;
            float x0r = re[r0], x0i = im[r0], x1r = re[r1], x1i = im[r1];
            if (((r0 >> (CB - 5)) & 1) == 0) {
                re[r0] = cs * x0r - ss * x1r;  im[r0] = cs * x0i - ss * x1i;
                re[r1] = ss * x0r + cs * x1r;  im[r1] = ss * x0i + cs * x1i;
            } else {
                re[r0] = -br * x0r + bi * x0i + ar * x1r - ai * x1i;
                im[r0] = -br * x0i - bi * x0r + ar * x1i + ai * x1r;
                re[r1] =  ar * x0r - ai * x0i + br * x1r - bi * x1i;
                im[r1] =  ar * x0i + ai * x0r + br * x1i + bi * x1r;
            }
        }
    } else {
        const bool side = (lane >> TB) & 1;
        if constexpr (CB >= 5) {
            float Bs = side ? ss : -ss;
            float Ar = side ? br : -br;
            float Ai = side ? bi : -bi;
#pragma unroll
            for (int r = 0; r < 8; r++) {
                float pr = __shfl_xor_sync(FULL, re[r], 1 << TB);
                float pi = __shfl_xor_sync(FULL, im[r], 1 << TB);
                if (((r >> (CB - 5)) & 1) == 0) {
                    re[r] = cs * re[r] + Bs * pr;
                    im[r] = cs * im[r] + Bs * pi;
                } else {
                    float xr = re[r], xi = im[r];
                    re[r] = Ar * xr - Ai * xi + ar * pr - ai * pi;
                    im[r] = Ar * xi + Ai * xr + ar * pi + ai * pr;
                }
            }
        } else {
            const bool c = (lane >> CB) & 1;
            float Ar, Ai, Br, Bi;
            if (c) { Ar = side ? br : -br; Ai = side ? bi : -bi; Br = ar; Bi = ai; }
            else   { Ar = cs; Ai = 0.f;    Br = side ? ss : -ss; Bi = 0.f; }
#pragma unroll
            for (int r = 0; r < 8; r++) {
                float pr = __shfl_xor_sync(FULL, re[r], 1 << TB);
                float pi = __shfl_xor_sync(FULL, im[r], 1 << TB);
                float xr = re[r], xi = im[r];
                re[r] = Ar * xr - Ai * xi + Br * pr - Bi * pi;
                im[r] = Ar * xi + Ai * xr + Br * pi + Bi * pr;
            }
        }
    }
}

// ===================== HMMA helpers =====================
__device__ __forceinline__ uint32_t smem_u32(const void* p) {
    uint32_t a;
    asm("{ .reg .u64 t; cvta.to.shared.u64 t, %1; cvt.u32.u64 %0, t; }" : "=r"(a) : "l"(p));
    return a;
}
__device__ __forceinline__ void ldsm_x4(uint32_t& r0, uint32_t& r1,
                                        uint32_t& r2, uint32_t& r3, uint32_t addr) {
    asm volatile("ldmatrix.sync.aligned.m8n8.x4.shared.b16 {%0,%1,%2,%3}, [%4];"
                 : "=r"(r0), "=r"(r1), "=r"(r2), "=r"(r3) : "r"(addr));
}
__device__ __forceinline__ void mma16816(float& c0, float& c1, float& c2, float& c3,
                                         uint32_t a0, uint32_t a1, uint32_t a2, uint32_t a3,
                                         uint32_t b0, uint32_t b1) {
    asm volatile("mma.sync.aligned.m16n8k16.row.col.f32.f16.f16.f32 "
                 "{%0,%1,%2,%3}, {%4,%5,%6,%7}, {%8,%9}, {%0,%1,%2,%3};"
                 : "+f"(c0), "+f"(c1), "+f"(c2), "+f"(c3)
                 : "r"(a0), "r"(a1), "r"(a2), "r"(a3), "r"(b0), "r"(b1));
}

// ===================== fused kernel =====================
// Work unit = (tile t, quarter q): tile = 128 batch rows, quarter = 64 output cols.
// 2048 units over 296 CTAs. Last 64 CTAs also build U (1 warp per column).
// In-kernel gmem barrier: 296 zeroing arrivals + 256 U-column arrivals = 552.
static constexpr int BROW = 264;                       // halfs per smem row (256 + 8 pad)
static constexpr int SMEM_TOTAL = 128 * BROW * 2;      // 67584 bytes
static constexpr int NCTA = 296;                       // 148 SMs x 2 CTAs (one full wave)
static constexpr int NUNITS = 2048;
static constexpr int CHUNK_HI = (NUNITS + NCTA - 1) / NCTA;            // 7
static constexpr int NHI = NUNITS - (CHUNK_HI - 1) * NCTA;             // 272 CTAs get 7
static constexpr int NBUILD = 64;                      // builder CTAs (tail of grid)
static constexpr int BARRIER_TARGET = NCTA + 256;      // 552
static constexpr int OUT4 = 65536 * 8 / 4;             // float4 count of out

__global__ void __launch_bounds__(128, 2)
qgemm(const float* __restrict__ x,
      const float* __restrict__ conv, const float* __restrict__ pool,
      float* __restrict__ out) {
    extern __shared__ __half smB[];
    __shared__ float scf[21 * 6];
    const uint32_t smb = smem_u32(smB);
    const int tid  = threadIdx.x;
    const int wid  = tid >> 5;
    const int lane = tid & 31;
    const int quad = lane & 3;       // t%4
    const int qrow = lane >> 2;      // t/4

    // ---- 1. all CTAs: zero a slice of out, then arrive
    for (int i = blockIdx.x * 128 + tid; i < OUT4; i += NCTA * 128)
        ((float4*)out)[i] = make_float4(0.f, 0.f, 0.f, 0.f);
    __threadfence();
    __syncthreads();
    if (tid == 0) atomicAdd(&g_count, 1);

    // ---- 2. builder CTAs: compute U columns (1 warp per column), arrive per warp
    if (blockIdx.x >= NCTA - NBUILD) {
        if (tid < 21) {
            int t = tid;
            float t0, t1, t2;
            if (t < 14)      { const float* p = conv + t * 3; t0 = p[0]; t1 = p[1]; t2 = p[2]; }
            else if (t < 18) { t0 = pool[0]; t1 = pool[1]; t2 = pool[2]; }
            else if (t < 20) { t0 = pool[3]; t1 = pool[4]; t2 = pool[5]; }
            else             { t0 = pool[6]; t1 = pool[7]; t2 = pool[8]; }
            float sg = 0.5f * (t1 + t2), dl = 0.5f * (t2 - t1);
            float cs = cosf(sg), ss = sinf(sg);
            float cd = cosf(dl), sd = sinf(dl);
            float cp = cosf(t0), sp = sinf(t0);
            float* o = scf + t * 6;
            o[0] = cs; o[1] = ss;
            o[2] = cp * cd; o[3] = sp * cd;
            o[4] = cp * sd; o[5] = sp * sd;
        }
        __syncthreads();

        const int k = (blockIdx.x - (NCTA - NBUILD)) * 4 + wid;   // column 0..255
        float re[8], im[8];
#pragma unroll
        for (int r = 0; r < 8; r++) {
            re[r] = (r == (k >> 5) && lane == (unsigned)(k & 31)) ? 1.f : 0.f;
            im[r] = 0.f;
        }
        apply_block<7, 6>(re, im, scf + 0 * 6, lane);
        apply_block<6, 5>(re, im, scf + 1 * 6, lane);
        apply_block<5, 4>(re, im, scf + 2 * 6, lane);
        apply_block<4, 3>(re, im, scf + 3 * 6, lane);
        apply_block<3, 2>(re, im, scf + 4 * 6, lane);
        apply_block<2, 1>(re, im, scf + 5 * 6, lane);
        apply_block<1, 0>(re, im, scf + 6 * 6, lane);
        apply_block<7, 6>(re, im, scf + 7 * 6, lane);
        apply_block<6, 5>(re, im, scf + 8 * 6, lane);
        apply_block<5, 4>(re, im, scf + 9 * 6, lane);
        apply_block<4, 3>(re, im, scf + 10 * 6, lane);
        apply_block<3, 2>(re, im, scf + 11 * 6, lane);
        apply_block<2, 1>(re, im, scf + 12 * 6, lane);
        apply_block<1, 0>(re, im, scf + 13 * 6, lane);
        apply_block<7, 3>(re, im, scf + 14 * 6, lane);
        apply_block<6, 2>(re, im, scf + 15 * 6, lane);
        apply_block<5, 1>(re, im, scf + 16 * 6, lane);
        apply_block<4, 0>(re, im, scf + 17 * 6, lane);
        apply_block<7, 5>(re, im, scf + 18 * 6, lane);
        apply_block<6, 4>(re, im, scf + 19 * 6, lane);
        apply_block<7, 6>(re, im, scf + 20 * 6, lane);
#pragma unroll
        for (int r = 0; r < 8; r++) {
            int i = (r << 5) | lane;
            g_Ure[i * 256 + k] = __float2half(re[r]);
            g_Uim[i * 256 + k] = __float2half(im[r]);
        }
        __threadfence();
        __syncwarp();
        if (lane == 0) atomicAdd(&g_count, 1);
    }

    // ---- 3. work schedule
    int myStart, myCount;
    if (blockIdx.x < NHI) { myStart = blockIdx.x * CHUNK_HI; myCount = CHUNK_HI; }
    else {
        myStart = NHI * CHUNK_HI + (blockIdx.x - NHI) * (CHUNK_HI - 1);
        myCount = CHUNK_HI - 1;
    }

    const int lgrp = lane >> 3, lrow = lane & 7;
    const uint32_t lbase = smb +
        (uint32_t)((((lgrp & 2) ? 64 : 0) + lrow) * BROW + (lgrp & 1) * 8) * 2;

    uint32_t A2[4][16][2];
    int last_t = -1;
    bool synced = false;

    float z7t[4], z4t[4], z3t[4], z2t[4], St[4], z1t[4], z0t[4];

    for (int u = myStart; u < myStart + myCount; u++) {
        const int t = u >> 2, q = u & 3;
        const int base = (t * 4 + wid) * 32;

        if (t != last_t) {
            // ---- flush previous tile's z to gmem
            if (last_t >= 0) {
                const int pbase = (last_t * 4 + wid) * 32;
#pragma unroll
                for (int rs = 0; rs < 4; rs++) {
                    float z[8];
                    z[0] = z0t[rs]; z[1] = z1t[rs]; z[2] = z2t[rs]; z[3] = z3t[rs];
                    z[4] = z4t[rs];
                    z[5] = ((quad >> 1) & 1) ? -St[rs] : St[rs];
                    z[6] = (quad & 1) ? -St[rs] : St[rs];
                    z[7] = z7t[rs];
#pragma unroll
                    for (int j = 0; j < 8; j++) {
                        z[j] += __shfl_xor_sync(FULL, z[j], 1);
                        z[j] += __shfl_xor_sync(FULL, z[j], 2);
                    }
                    const int row = pbase + qrow + rs * 8;
                    atomicAdd(out + (size_t)row * 8 + 2 * quad,     z[2 * quad]);
                    atomicAdd(out + (size_t)row * 8 + 2 * quad + 1, z[2 * quad + 1]);
                }
            }
#pragma unroll
            for (int rs = 0; rs < 4; rs++) {
                z7t[rs] = 0.f; z4t[rs] = 0.f; z3t[rs] = 0.f; z2t[rs] = 0.f;
                St[rs] = 0.f; z1t[rs] = 0.f; z0t[rs] = 0.f;
            }
            last_t = t;

            // ---- build A fragments for this tile (indep of U)
#pragma unroll
            for (int rs = 0; rs < 4; rs++) {
                const int row = base + qrow + rs * 8;
                const float4* xp = (const float4*)(x + (size_t)row * 8);
                float4 x0 = xp[0], x1 = xp[1];
                float xv[8] = {x0.x, x0.y, x0.z, x0.w, x1.x, x1.y, x1.z, x1.w};
                float c_[8], s_[8];
#pragma unroll
                for (int qq = 0; qq < 8; qq++) __sincosf(0.5f * xv[qq], &s_[qq], &c_[qq]);
                float hi16[16];
#pragma unroll
                for (int h = 0; h < 16; h++)
                    hi16[h] = ((h & 8) ? s_[0] : c_[0]) * ((h & 4) ? s_[1] : c_[1]) *
                              ((h & 2) ? s_[2] : c_[2]) * ((h & 1) ? s_[3] : c_[3]);
                float q5 = (quad & 2) ? s_[5] : c_[5];
                float q6 = (quad & 1) ? s_[6] : c_[6];
                float m56 = q5 * q6;
                float l00 = c_[4] * m56 * c_[7], l01 = c_[4] * m56 * s_[7];
                float l10 = s_[4] * m56 * c_[7], l11 = s_[4] * m56 * s_[7];
#pragma unroll
                for (int kk = 0; kk < 16; kk++) {
                    float h = hi16[kk];
                    __half2 plo = __floats2half2_rn(h * l00, h * l01);
                    __half2 phi = __floats2half2_rn(h * l10, h * l11);
                    A2[rs][kk][0] = *(uint32_t*)&plo;
                    A2[rs][kk][1] = *(uint32_t*)&phi;
                }
            }
        }

        // ---- barrier: wait for zeroing + all U columns (overlapped with A build)
        if (!synced) {
            if (tid == 0) {
                while (atomicAdd(&g_count, 0) < BARRIER_TARGET) {}
            }
            __syncthreads();
            __threadfence();
            synced = true;
        }

        // ---- B quarter q: smem rows 0-63 = Ure[n0..], 64-127 = Uim[n0..]
        const int n0 = q * 64;
#pragma unroll
        for (int j = 0; j < 32; j++) {
            int c = j * 128 + tid;
            int row = c >> 5, kc = (c & 31) * 8;
            const __half* src = (row < 64) ? (g_Ure + (size_t)(n0 + row) * 256 + kc)
                                           : (g_Uim + (size_t)(n0 + row - 64) * 256 + kc);
            *(uint4*)(smB + row * BROW + kc) = *(const uint4*)src;
        }
        __syncthreads();

        // ---- mainloop over the 8 n-tiles of this quarter
#pragma unroll
        for (int nt = 0; nt < 8; nt++) {
            float cre_e[8] = {0,0,0,0,0,0,0,0}, cim_e[8] = {0,0,0,0,0,0,0,0};
            float cre_o[8] = {0,0,0,0,0,0,0,0}, cim_o[8] = {0,0,0,0,0,0,0,0};
            uint32_t bufA[4], bufB[4];
            ldsm_x4(bufA[0], bufA[1], bufA[2], bufA[3],
                    lbase + (uint32_t)(nt * 8 * BROW) * 2);
#pragma unroll
            for (int kk = 0; kk < 16; kk++) {
                uint32_t* cur = (kk & 1) ? bufB : bufA;
                uint32_t* nxt = (kk & 1) ? bufA : bufB;
                if (kk < 15)
                    ldsm_x4(nxt[0], nxt[1], nxt[2], nxt[3],
                            lbase + (uint32_t)(nt * 8 * BROW + (kk + 1) * 16) * 2);
                float* cr = (kk & 1) ? cre_o : cre_e;
                float* ci = (kk & 1) ? cim_o : cim_e;
                mma16816(cr[0], cr[1], cr[2], cr[3],
                         A2[0][kk][0], A2[1][kk][0], A2[0][kk][1], A2[1][kk][1],
                         cur[0], cur[1]);
                mma16816(cr[4], cr[5], cr[6], cr[7],
                         A2[2][kk][0], A2[3][kk][0], A2[2][kk][1], A2[3][kk][1],
                         cur[0], cur[1]);
                mma16816(ci[0], ci[1], ci[2], ci[3],
                         A2[0][kk][0], A2[1][kk][0], A2[0][kk][1], A2[1][kk][1],
                         cur[2], cur[3]);
                mma16816(ci[4], ci[5], ci[6], ci[7],
                         A2[2][kk][0], A2[3][kk][0], A2[2][kk][1], A2[3][kk][1],
                         cur[2], cur[3]);
            }
#pragma unroll
            for (int rs = 0; rs < 4; rs++) {
                float r0 = cre_e[2*rs]   + cre_o[2*rs];
                float r1 = cre_e[2*rs+1] + cre_o[2*rs+1];
                float i0 = cim_e[2*rs]   + cim_o[2*rs];
                float i1 = cim_e[2*rs+1] + cim_o[2*rs+1];
                float p0 = r0 * r0 + i0 * i0;
                float p1 = r1 * r1 + i1 * i1;
                float d = p0 - p1, s = p0 + p1;
                z7t[rs] += d;
                St[rs] += s;
                z4t[rs] += (nt & 1) ? -s : s;
                z3t[rs] += (nt & 2) ? -s : s;
                z2t[rs] += (nt & 4) ? -s : s;
                z1t[rs] += (q & 1) ? -s : s;
                z0t[rs] += (q & 2) ? -s : s;
            }
        }
        __syncthreads();   // before next unit overwrites smB
    }

    // ---- final flush
    if (last_t >= 0) {
        const int pbase = (last_t * 4 + wid) * 32;
#pragma unroll
        for (int rs = 0; rs < 4; rs++) {
            float z[8];
            z[0] = z0t[rs]; z[1] = z1t[rs]; z[2] = z2t[rs]; z[3] = z3t[rs];
            z[4] = z4t[rs];
            z[5] = ((quad >> 1) & 1) ? -St[rs] : St[rs];
            z[6] = (quad & 1) ? -St[rs] : St[rs];
            z[7] = z7t[rs];
#pragma unroll
            for (int j = 0; j < 8; j++) {
                z[j] += __shfl_xor_sync(FULL, z[j], 1);
                z[j] += __shfl_xor_sync(FULL, z[j], 2);
            }
            const int row = pbase + qrow + rs * 8;
            atomicAdd(out + (size_t)row * 8 + 2 * quad,     z[2 * quad]);
            atomicAdd(out + (size_t)row * 8 + 2 * quad + 1, z[2 * quad + 1]);
        }
    }

    // ---- self-reset of barrier counters (last CTA to finish)
    __syncthreads();
    if (tid == 0) {
        int d = atomicAdd(&g_done, 1);
        if (d == NCTA - 1) {
            g_count = 0;
            g_done  = 0;
            __threadfence();
        }
    }
}

// ===================== host launcher =====================
extern "C" void kernel_launch(void* const* d_in, const int* in_sizes, int n_in,
                              void* d_out, int out_size) {
    const float* x    = (const float*)d_in[0];
    const float* conv = (const float*)d_in[1];
    const float* pool = (const float*)d_in[2];
    float* out = (float*)d_out;

    static bool attr_set = false;
    if (!attr_set) {
        cudaFuncSetAttribute(qgemm, cudaFuncAttributeMaxDynamicSharedMemorySize, SMEM_TOTAL);
        attr_set = true;
    }

    qgemm<<<NCTA, 128, SMEM_TOTAL>>>(x, conv, pool, out);
}

// round 16
// speedup vs baseline: 1.0638x; 1.0638x over previous
#include <cuda_runtime.h>
#include <cuda_fp16.h>
#include <cstdint>
#include <math.h>

#define FULL 0xffffffffu

// ===================== device globals =====================
__device__ __half g_Ure[256 * 256];        // U_re[i][k], K-major
__device__ __half g_Uim[256 * 256];        // U_im[i][k], K-major

// ===================== scalar fused-block sim (validated R1/R6) =====================
template<int CB, int TB>
__device__ __forceinline__ void apply_block(float (&re)[8], float (&im)[8],
                                            const float* cf, unsigned lane) {
    float cs = cf[0], ss = cf[1];
    float ar = cf[2], ai = cf[3], br = cf[4], bi = cf[5];
    if constexpr (TB >= 5) {
        static_assert(CB >= 5, "in-lane target gates have in-register control");
        constexpr int tm = 1 << (TB - 5);
#pragma unroll
        for (int r0 = 0; r0 < 8; r0++) {
            if (r0 & tm) continue;
            const int r1 = r0 | tm;
            float x0r = re[r0], x0i = im[r0], x1r = re[r1], x1i = im[r1];
            if (((r0 >> (CB - 5)) & 1) == 0) {
                re[r0] = cs * x0r - ss * x1r;  im[r0] = cs * x0i - ss * x1i;
                re[r1] = ss * x0r + cs * x1r;  im[r1] = ss * x0i + cs * x1i;
            } else {
                re[r0] = -br * x0r + bi * x0i + ar * x1r - ai * x1i;
                im[r0] = -br * x0i - bi * x0r + ar * x1i + ai * x1r;
                re[r1] =  ar * x0r - ai * x0i + br * x1r - bi * x1i;
                im[r1] =  ar * x0i + ai * x0r + br * x1i + bi * x1r;
            }
        }
    } else {
        const bool side = (lane >> TB) & 1;
        if constexpr (CB >= 5) {
            float Bs = side ? ss : -ss;
            float Ar = side ? br : -br;
            float Ai = side ? bi : -bi;
#pragma unroll
            for (int r = 0; r < 8; r++) {
                float pr = __shfl_xor_sync(FULL, re[r], 1 << TB);
                float pi = __shfl_xor_sync(FULL, im[r], 1 << TB);
                if (((r >> (CB - 5)) & 1) == 0) {
                    re[r] = cs * re[r] + Bs * pr;
                    im[r] = cs * im[r] + Bs * pi;
                } else {
                    float xr = re[r], xi = im[r];
                    re[r] = Ar * xr - Ai * xi + ar * pr - ai * pi;
                    im[r] = Ar * xi + Ai * xr + ar * pi + ai * pr;
                }
            }
        } else {
            const bool c = (lane >> CB) & 1;
            float Ar, Ai, Br, Bi;
            if (c) { Ar = side ? br : -br; Ai = side ? bi : -bi; Br = ar; Bi = ai; }
            else   { Ar = cs; Ai = 0.f;    Br = side ? ss : -ss; Bi = 0.f; }
#pragma unroll
            for (int r = 0; r < 8; r++) {
                float pr = __shfl_xor_sync(FULL, re[r], 1 << TB);
                float pi = __shfl_xor_sync(FULL, im[r], 1 << TB);
                float xr = re[r], xi = im[r];
                re[r] = Ar * xr - Ai * xi + Br * pr - Bi * pi;
                im[r] = Ar * xi + Ai * xr + Br * pi + Bi * pr;
            }
        }
    }
}

// build U columns (coef computation fused); one warp per basis column
__global__ void build_u(const float* __restrict__ conv,
                        const float* __restrict__ pool) {
    __shared__ float scf[21 * 6];
    {
        int t = threadIdx.x;
        if (t < 21) {
            float t0, t1, t2;
            if (t < 14)      { const float* p = conv + t * 3; t0 = p[0]; t1 = p[1]; t2 = p[2]; }
            else if (t < 18) { t0 = pool[0]; t1 = pool[1]; t2 = pool[2]; }
            else if (t < 20) { t0 = pool[3]; t1 = pool[4]; t2 = pool[5]; }
            else             { t0 = pool[6]; t1 = pool[7]; t2 = pool[8]; }
            float sg = 0.5f * (t1 + t2), dl = 0.5f * (t2 - t1);
            float cs, ss, cd, sd, cp, sp;
            __sincosf(sg, &ss, &cs);
            __sincosf(dl, &sd, &cd);
            __sincosf(t0, &sp, &cp);
            float* o = scf + t * 6;
            o[0] = cs; o[1] = ss;
            o[2] = cp * cd; o[3] = sp * cd;
            o[4] = cp * sd; o[5] = sp * sd;
        }
    }
    __syncthreads();

    // let the dependent qgemm grid launch now; it grid-syncs on our completion
    cudaTriggerProgrammaticLaunchCompletion();

    const int wid = threadIdx.x >> 5;
    const unsigned lane = threadIdx.x & 31;
    const int k = blockIdx.x * (blockDim.x >> 5) + wid;
    float re[8], im[8];
#pragma unroll
    for (int r = 0; r < 8; r++) {
        re[r] = (r == (k >> 5) && lane == (unsigned)(k & 31)) ? 1.f : 0.f;
        im[r] = 0.f;
    }
    apply_block<7, 6>(re, im, scf + 0 * 6, lane);
    apply_block<6, 5>(re, im, scf + 1 * 6, lane);
    apply_block<5, 4>(re, im, scf + 2 * 6, lane);
    apply_block<4, 3>(re, im, scf + 3 * 6, lane);
    apply_block<3, 2>(re, im, scf + 4 * 6, lane);
    apply_block<2, 1>(re, im, scf + 5 * 6, lane);
    apply_block<1, 0>(re, im, scf + 6 * 6, lane);
    apply_block<7, 6>(re, im, scf + 7 * 6, lane);
    apply_block<6, 5>(re, im, scf + 8 * 6, lane);
    apply_block<5, 4>(re, im, scf + 9 * 6, lane);
    apply_block<4, 3>(re, im, scf + 10 * 6, lane);
    apply_block<3, 2>(re, im, scf + 11 * 6, lane);
    apply_block<2, 1>(re, im, scf + 12 * 6, lane);
    apply_block<1, 0>(re, im, scf + 13 * 6, lane);
    apply_block<7, 3>(re, im, scf + 14 * 6, lane);
    apply_block<6, 2>(re, im, scf + 15 * 6, lane);
    apply_block<5, 1>(re, im, scf + 16 * 6, lane);
    apply_block<4, 0>(re, im, scf + 17 * 6, lane);
    apply_block<7, 5>(re, im, scf + 18 * 6, lane);
    apply_block<6, 4>(re, im, scf + 19 * 6, lane);
    apply_block<7, 6>(re, im, scf + 20 * 6, lane);
#pragma unroll
    for (int r = 0; r < 8; r++) {
        int i = (r << 5) | lane;
        g_Ure[i * 256 + k] = __float2half(re[r]);
        g_Uim[i * 256 + k] = __float2half(im[r]);
    }
}

// ===================== HMMA helpers =====================
__device__ __forceinline__ uint32_t smem_u32(const void* p) {
    uint32_t a;
    asm("{ .reg .u64 t; cvta.to.shared.u64 t, %1; cvt.u32.u64 %0, t; }" : "=r"(a) : "l"(p));
    return a;
}
__device__ __forceinline__ void ldsm_x4(uint32_t& r0, uint32_t& r1,
                                        uint32_t& r2, uint32_t& r3, uint32_t addr) {
    asm volatile("ldmatrix.sync.aligned.m8n8.x4.shared.b16 {%0,%1,%2,%3}, [%4];"
                 : "=r"(r0), "=r"(r1), "=r"(r2), "=r"(r3) : "r"(addr));
}
__device__ __forceinline__ void mma16816(float& c0, float& c1, float& c2, float& c3,
                                         uint32_t a0, uint32_t a1, uint32_t a2, uint32_t a3,
                                         uint32_t b0, uint32_t b1) {
    asm volatile("mma.sync.aligned.m16n8k16.row.col.f32.f16.f16.f32 "
                 "{%0,%1,%2,%3}, {%4,%5,%6,%7}, {%8,%9}, {%0,%1,%2,%3};"
                 : "+f"(c0), "+f"(c1), "+f"(c2), "+f"(c3)
                 : "r"(a0), "r"(a1), "r"(a2), "r"(a3), "r"(b0), "r"(b1));
}

// ===================== main GEMM kernel =====================
// Work unit = (tile t, quarter q): tile = 128 batch rows, quarter = 64 output cols.
// 2048 units over 296 CTAs; z accumulated per tile, flushed on tile change.
static constexpr int BROW = 264;                       // halfs per smem row (256 + 8 pad)
static constexpr int SMEM_TOTAL = 128 * BROW * 2;      // 67584 bytes
static constexpr int NCTA = 296;                       // 148 SMs x 2 CTAs
static constexpr int NUNITS = 2048;
static constexpr int CHUNK_HI = (NUNITS + NCTA - 1) / NCTA;            // 7
static constexpr int NHI = NUNITS - (CHUNK_HI - 1) * NCTA;             // 272 CTAs get 7

__global__ void __launch_bounds__(128, 2)
qgemm(const float* __restrict__ x, float* __restrict__ out) {
    extern __shared__ __half smB[];
    const uint32_t smb = smem_u32(smB);
    const int tid  = threadIdx.x;
    const int wid  = tid >> 5;
    const int lane = tid & 31;
    const int quad = lane & 3;       // t%4
    const int qrow = lane >> 2;      // t/4

    int myStart, myCount;
    if (blockIdx.x < NHI) { myStart = blockIdx.x * CHUNK_HI; myCount = CHUNK_HI; }
    else {
        myStart = NHI * CHUNK_HI + (blockIdx.x - NHI) * (CHUNK_HI - 1);
        myCount = CHUNK_HI - 1;
    }

    const int lgrp = lane >> 3, lrow = lane & 7;
    const uint32_t lbase = smb +
        (uint32_t)((((lgrp & 2) ? 64 : 0) + lrow) * BROW + (lgrp & 1) * 8) * 2;

    uint32_t A2[4][16][2];
    int last_t = -1;
    bool synced = false;

    // per-tile accumulators
    float z7t[4], z4t[4], z3t[4], z2t[4], St[4], z1t[4], z0t[4];

    for (int u = myStart; u < myStart + myCount; u++) {
        const int t = u >> 2, q = u & 3;
        const int base = (t * 4 + wid) * 32;

        if (t != last_t) {
            // ---- flush previous tile's z to gmem
            if (last_t >= 0) {
                const int pbase = (last_t * 4 + wid) * 32;
#pragma unroll
                for (int rs = 0; rs < 4; rs++) {
                    float z[8];
                    z[0] = z0t[rs]; z[1] = z1t[rs]; z[2] = z2t[rs]; z[3] = z3t[rs];
                    z[4] = z4t[rs];
                    z[5] = ((quad >> 1) & 1) ? -St[rs] : St[rs];
                    z[6] = (quad & 1) ? -St[rs] : St[rs];
                    z[7] = z7t[rs];
#pragma unroll
                    for (int j = 0; j < 8; j++) {
                        z[j] += __shfl_xor_sync(FULL, z[j], 1);
                        z[j] += __shfl_xor_sync(FULL, z[j], 2);
                    }
                    const int row = pbase + qrow + rs * 8;
                    atomicAdd(out + (size_t)row * 8 + 2 * quad,     z[2 * quad]);
                    atomicAdd(out + (size_t)row * 8 + 2 * quad + 1, z[2 * quad + 1]);
                }
            }
#pragma unroll
            for (int rs = 0; rs < 4; rs++) {
                z7t[rs] = 0.f; z4t[rs] = 0.f; z3t[rs] = 0.f; z2t[rs] = 0.f;
                St[rs] = 0.f; z1t[rs] = 0.f; z0t[rs] = 0.f;
            }
            last_t = t;

            // ---- build A fragments for this tile.
            // Quad-mates (lane&~3) need the SAME 4 rows; each thread computes
            // sincos for only row rs=quad, then shares via quad shuffles (MUFU/4).
            float sc[8], cc[8];
            {
                const int myrow = base + qrow + quad * 8;
                const float4* xp = (const float4*)(x + (size_t)myrow * 8);
                float4 x0 = xp[0], x1 = xp[1];
                float xv[8] = {x0.x, x0.y, x0.z, x0.w, x1.x, x1.y, x1.z, x1.w};
#pragma unroll
                for (int qq = 0; qq < 8; qq++)
                    __sincosf(0.5f * xv[qq], &sc[qq], &cc[qq]);
            }
#pragma unroll
            for (int rs = 0; rs < 4; rs++) {
                const int src = (lane & ~3) | rs;
                float c_[8], s_[8];
#pragma unroll
                for (int qq = 0; qq < 8; qq++) {
                    c_[qq] = __shfl_sync(FULL, cc[qq], src);
                    s_[qq] = __shfl_sync(FULL, sc[qq], src);
                }
                float hi16[16];
#pragma unroll
                for (int h = 0; h < 16; h++)
                    hi16[h] = ((h & 8) ? s_[0] : c_[0]) * ((h & 4) ? s_[1] : c_[1]) *
                              ((h & 2) ? s_[2] : c_[2]) * ((h & 1) ? s_[3] : c_[3]);
                float q5 = (quad & 2) ? s_[5] : c_[5];
                float q6 = (quad & 1) ? s_[6] : c_[6];
                float m56 = q5 * q6;
                float l00 = c_[4] * m56 * c_[7], l01 = c_[4] * m56 * s_[7];
                float l10 = s_[4] * m56 * c_[7], l11 = s_[4] * m56 * s_[7];
#pragma unroll
                for (int kk = 0; kk < 16; kk++) {
                    float h = hi16[kk];
                    __half2 plo = __floats2half2_rn(h * l00, h * l01);
                    __half2 phi = __floats2half2_rn(h * l10, h * l11);
                    A2[rs][kk][0] = *(uint32_t*)&plo;
                    A2[rs][kk][1] = *(uint32_t*)&phi;
                }
            }
        }

        // wait for build_u completion before first U read (overlaps A build above)
        if (!synced) { cudaGridDependencySynchronize(); synced = true; }

        // ---- B quarter q: smem rows 0-63 = Ure[n0..], 64-127 = Uim[n0..]
        const int n0 = q * 64;
#pragma unroll
        for (int j = 0; j < 32; j++) {
            int c = j * 128 + tid;
            int row = c >> 5, kc = (c & 31) * 8;
            const __half* src = (row < 64) ? (g_Ure + (size_t)(n0 + row) * 256 + kc)
                                           : (g_Uim + (size_t)(n0 + row - 64) * 256 + kc);
            *(uint4*)(smB + row * BROW + kc) = *(const uint4*)src;
        }
        __syncthreads();

        // ---- mainloop over the 8 n-tiles of this quarter
#pragma unroll
        for (int nt = 0; nt < 8; nt++) {
            float cre_e[8] = {0,0,0,0,0,0,0,0}, cim_e[8] = {0,0,0,0,0,0,0,0};
            float cre_o[8] = {0,0,0,0,0,0,0,0}, cim_o[8] = {0,0,0,0,0,0,0,0};
            uint32_t bufA[4], bufB[4];
            ldsm_x4(bufA[0], bufA[1], bufA[2], bufA[3],
                    lbase + (uint32_t)(nt * 8 * BROW) * 2);
#pragma unroll
            for (int kk = 0; kk < 16; kk++) {
                uint32_t* cur = (kk & 1) ? bufB : bufA;
                uint32_t* nxt = (kk & 1) ? bufA : bufB;
                if (kk < 15)
                    ldsm_x4(nxt[0], nxt[1], nxt[2], nxt[3],
                            lbase + (uint32_t)(nt * 8 * BROW + (kk + 1) * 16) * 2);
                float* cr = (kk & 1) ? cre_o : cre_e;
                float* ci = (kk & 1) ? cim_o : cim_e;
                mma16816(cr[0], cr[1], cr[2], cr[3],
                         A2[0][kk][0], A2[1][kk][0], A2[0][kk][1], A2[1][kk][1],
                         cur[0], cur[1]);
                mma16816(cr[4], cr[5], cr[6], cr[7],
                         A2[2][kk][0], A2[3][kk][0], A2[2][kk][1], A2[3][kk][1],
                         cur[0], cur[1]);
                mma16816(ci[0], ci[1], ci[2], ci[3],
                         A2[0][kk][0], A2[1][kk][0], A2[0][kk][1], A2[1][kk][1],
                         cur[2], cur[3]);
                mma16816(ci[4], ci[5], ci[6], ci[7],
                         A2[2][kk][0], A2[3][kk][0], A2[2][kk][1], A2[3][kk][1],
                         cur[2], cur[3]);
            }
#pragma unroll
            for (int rs = 0; rs < 4; rs++) {
                float r0 = cre_e[2*rs]   + cre_o[2*rs];
                float r1 = cre_e[2*rs+1] + cre_o[2*rs+1];
                float i0 = cim_e[2*rs]   + cim_o[2*rs];
                float i1 = cim_e[2*rs+1] + cim_o[2*rs+1];
                float p0 = r0 * r0 + i0 * i0;
                float p1 = r1 * r1 + i1 * i1;
                float d = p0 - p1, s = p0 + p1;
                z7t[rs] += d;
                St[rs] += s;
                z4t[rs] += (nt & 1) ? -s : s;
                z3t[rs] += (nt & 2) ? -s : s;
                z2t[rs] += (nt & 4) ? -s : s;
                z1t[rs] += (q & 1) ? -s : s;
                z0t[rs] += (q & 2) ? -s : s;
            }
        }
        __syncthreads();   // before next unit overwrites smB
    }

    // ---- final flush
    if (last_t >= 0) {
        const int pbase = (last_t * 4 + wid) * 32;
#pragma unroll
        for (int rs = 0; rs < 4; rs++) {
            float z[8];
            z[0] = z0t[rs]; z[1] = z1t[rs]; z[2] = z2t[rs]; z[3] = z3t[rs];
            z[4] = z4t[rs];
            z[5] = ((quad >> 1) & 1) ? -St[rs] : St[rs];
            z[6] = (quad & 1) ? -St[rs] : St[rs];
            z[7] = z7t[rs];
#pragma unroll
            for (int j = 0; j < 8; j++) {
                z[j] += __shfl_xor_sync(FULL, z[j], 1);
                z[j] += __shfl_xor_sync(FULL, z[j], 2);
            }
            const int row = pbase + qrow + rs * 8;
            atomicAdd(out + (size_t)row * 8 + 2 * quad,     z[2 * quad]);
            atomicAdd(out + (size_t)row * 8 + 2 * quad + 1, z[2 * quad + 1]);
        }
    }
}

// ===================== host launcher =====================
extern "C" void kernel_launch(void* const* d_in, const int* in_sizes, int n_in,
                              void* d_out, int out_size) {
    const float* x    = (const float*)d_in[0];
    const float* conv = (const float*)d_in[1];
    const float* pool = (const float*)d_in[2];
    float* out = (float*)d_out;

    // zero output (accumulated via atomics); memset node off build_u's critical path
    cudaMemsetAsync(d_out, 0, (size_t)out_size * sizeof(float), 0);

    build_u<<<128, 64>>>(conv, pool);

    static bool attr_set = false;
    if (!attr_set) {
        cudaFuncSetAttribute(qgemm, cudaFuncAttributeMaxDynamicSharedMemorySize, SMEM_TOTAL);
        attr_set = true;
    }

    cudaLaunchConfig_t cfg = {};
    cfg.gridDim = dim3(NCTA, 1, 1);
    cfg.blockDim = dim3(128, 1, 1);
    cfg.dynamicSmemBytes = SMEM_TOTAL;
    cfg.stream = 0;
    cudaLaunchAttribute attrs[1];
    attrs[0].id = cudaLaunchAttributeProgrammaticStreamSerialization;
    attrs[0].val.programmaticStreamSerializationAllowed = 1;
    cfg.attrs = attrs;
    cfg.numAttrs = 1;
    cudaLaunchKernelEx(&cfg, qgemm, x, out);
}

// round 17
// speedup vs baseline: 1.0747x; 1.0102x over previous
#include <cuda_runtime.h>
#include <cuda_fp16.h>
#include <cstdint>
#include <math.h>

#define FULL 0xffffffffu

// ===================== device globals =====================
__device__ __half g_Ure[256 * 256];        // U_re[i][k], K-major
__device__ __half g_Uim[256 * 256];        // U_im[i][k], K-major

// ===================== scalar fused-block sim (validated R1/R6) =====================
template<int CB, int TB>
__device__ __forceinline__ void apply_block(float (&re)[8], float (&im)[8],
                                            const float* cf, unsigned lane) {
    float cs = cf[0], ss = cf[1];
    float ar = cf[2], ai = cf[3], br = cf[4], bi = cf[5];
    if constexpr (TB >= 5) {
        static_assert(CB >= 5, "in-lane target gates have in-register control");
        constexpr int tm = 1 << (TB - 5);
#pragma unroll
        for (int r0 = 0; r0 < 8; r0++) {
            if (r0 & tm) continue;
            const int r1 = r0 | tm;
            float x0r = re[r0], x0i = im[r0], x1r = re[r1], x1i = im[r1];
            if (((r0 >> (CB - 5)) & 1) == 0) {
                re[r0] = cs * x0r - ss * x1r;  im[r0] = cs * x0i - ss * x1i;
                re[r1] = ss * x0r + cs * x1r;  im[r1] = ss * x0i + cs * x1i;
            } else {
                re[r0] = -br * x0r + bi * x0i + ar * x1r - ai * x1i;
                im[r0] = -br * x0i - bi * x0r + ar * x1i + ai * x1r;
                re[r1] =  ar * x0r - ai * x0i + br * x1r - bi * x1i;
                im[r1] =  ar * x0i + ai * x0r + br * x1i + bi * x1r;
            }
        }
    } else {
        const bool side = (lane >> TB) & 1;
        if constexpr (CB >= 5) {
            float Bs = side ? ss : -ss;
            float Ar = side ? br : -br;
            float Ai = side ? bi : -bi;
#pragma unroll
            for (int r = 0; r < 8; r++) {
                float pr = __shfl_xor_sync(FULL, re[r], 1 << TB);
                float pi = __shfl_xor_sync(FULL, im[r], 1 << TB);
                if (((r >> (CB - 5)) & 1) == 0) {
                    re[r] = cs * re[r] + Bs * pr;
                    im[r] = cs * im[r] + Bs * pi;
                } else {
                    float xr = re[r], xi = im[r];
                    re[r] = Ar * xr - Ai * xi + ar * pr - ai * pi;
                    im[r] = Ar * xi + Ai * xr + ar * pi + ai * pr;
                }
            }
        } else {
            const bool c = (lane >> CB) & 1;
            float Ar, Ai, Br, Bi;
            if (c) { Ar = side ? br : -br; Ai = side ? bi : -bi; Br = ar; Bi = ai; }
            else   { Ar = cs; Ai = 0.f;    Br = side ? ss : -ss; Bi = 0.f; }
#pragma unroll
            for (int r = 0; r < 8; r++) {
                float pr = __shfl_xor_sync(FULL, re[r], 1 << TB);
                float pi = __shfl_xor_sync(FULL, im[r], 1 << TB);
                float xr = re[r], xi = im[r];
                re[r] = Ar * xr - Ai * xi + Br * pr - Bi * pi;
                im[r] = Ar * xi + Ai * xr + Br * pi + Bi * pr;
            }
        }
    }
}

// build U columns (coef computation fused); one warp per block, one column per block
__global__ void build_u(const float* __restrict__ conv,
                        const float* __restrict__ pool) {
    __shared__ float scf[21 * 6];
    {
        int t = threadIdx.x;
        if (t < 21) {
            float t0, t1, t2;
            if (t < 14)      { const float* p = conv + t * 3; t0 = p[0]; t1 = p[1]; t2 = p[2]; }
            else if (t < 18) { t0 = pool[0]; t1 = pool[1]; t2 = pool[2]; }
            else if (t < 20) { t0 = pool[3]; t1 = pool[4]; t2 = pool[5]; }
            else             { t0 = pool[6]; t1 = pool[7]; t2 = pool[8]; }
            float sg = 0.5f * (t1 + t2), dl = 0.5f * (t2 - t1);
            float cs, ss, cd, sd, cp, sp;
            __sincosf(sg, &ss, &cs);
            __sincosf(dl, &sd, &cd);
            __sincosf(t0, &sp, &cp);
            float* o = scf + t * 6;
            o[0] = cs; o[1] = ss;
            o[2] = cp * cd; o[3] = sp * cd;
            o[4] = cp * sd; o[5] = sp * sd;
        }
    }
    __syncwarp();

    // let the dependent qgemm grid launch now; it grid-syncs on our completion
    cudaTriggerProgrammaticLaunchCompletion();

    const unsigned lane = threadIdx.x & 31;
    const int k = blockIdx.x;
    float re[8], im[8];
#pragma unroll
    for (int r = 0; r < 8; r++) {
        re[r] = (r == (k >> 5) && lane == (unsigned)(k & 31)) ? 1.f : 0.f;
        im[r] = 0.f;
    }
    apply_block<7, 6>(re, im, scf + 0 * 6, lane);
    apply_block<6, 5>(re, im, scf + 1 * 6, lane);
    apply_block<5, 4>(re, im, scf + 2 * 6, lane);
    apply_block<4, 3>(re, im, scf + 3 * 6, lane);
    apply_block<3, 2>(re, im, scf + 4 * 6, lane);
    apply_block<2, 1>(re, im, scf + 5 * 6, lane);
    apply_block<1, 0>(re, im, scf + 6 * 6, lane);
    apply_block<7, 6>(re, im, scf + 7 * 6, lane);
    apply_block<6, 5>(re, im, scf + 8 * 6, lane);
    apply_block<5, 4>(re, im, scf + 9 * 6, lane);
    apply_block<4, 3>(re, im, scf + 10 * 6, lane);
    apply_block<3, 2>(re, im, scf + 11 * 6, lane);
    apply_block<2, 1>(re, im, scf + 12 * 6, lane);
    apply_block<1, 0>(re, im, scf + 13 * 6, lane);
    apply_block<7, 3>(re, im, scf + 14 * 6, lane);
    apply_block<6, 2>(re, im, scf + 15 * 6, lane);
    apply_block<5, 1>(re, im, scf + 16 * 6, lane);
    apply_block<4, 0>(re, im, scf + 17 * 6, lane);
    apply_block<7, 5>(re, im, scf + 18 * 6, lane);
    apply_block<6, 4>(re, im, scf + 19 * 6, lane);
    apply_block<7, 6>(re, im, scf + 20 * 6, lane);
#pragma unroll
    for (int r = 0; r < 8; r++) {
        int i = (r << 5) | lane;
        g_Ure[i * 256 + k] = __float2half(re[r]);
        g_Uim[i * 256 + k] = __float2half(im[r]);
    }
}

// ===================== HMMA helpers =====================
__device__ __forceinline__ uint32_t smem_u32(const void* p) {
    uint32_t a;
    asm("{ .reg .u64 t; cvta.to.shared.u64 t, %1; cvt.u32.u64 %0, t; }" : "=r"(a) : "l"(p));
    return a;
}
__device__ __forceinline__ void ldsm_x4(uint32_t& r0, uint32_t& r1,
                                        uint32_t& r2, uint32_t& r3, uint32_t addr) {
    asm volatile("ldmatrix.sync.aligned.m8n8.x4.shared.b16 {%0,%1,%2,%3}, [%4];"
                 : "=r"(r0), "=r"(r1), "=r"(r2), "=r"(r3) : "r"(addr));
}
__device__ __forceinline__ void mma16816(float& c0, float& c1, float& c2, float& c3,
                                         uint32_t a0, uint32_t a1, uint32_t a2, uint32_t a3,
                                         uint32_t b0, uint32_t b1) {
    asm volatile("mma.sync.aligned.m16n8k16.row.col.f32.f16.f16.f32 "
                 "{%0,%1,%2,%3}, {%4,%5,%6,%7}, {%8,%9}, {%0,%1,%2,%3};"
                 : "+f"(c0), "+f"(c1), "+f"(c2), "+f"(c3)
                 : "r"(a0), "r"(a1), "r"(a2), "r"(a3), "r"(b0), "r"(b1));
}

// ===================== main GEMM kernel =====================
// Work unit = (tile t, quarter q): tile = 128 batch rows, quarter = 64 output cols.
// 2048 units over 296 CTAs (98.8% balance); per-UNIT epilogue flush (R12 best-total).
static constexpr int BROW = 264;                       // halfs per smem row (256 + 8 pad)
static constexpr int SMEM_TOTAL = 128 * BROW * 2;      // 67584 bytes
static constexpr int NCTA = 296;                       // 148 SMs x 2 CTAs
static constexpr int NUNITS = 2048;
static constexpr int CHUNK_HI = (NUNITS + NCTA - 1) / NCTA;            // 7
static constexpr int NHI = NUNITS - (CHUNK_HI - 1) * NCTA;             // 272 CTAs get 7

__global__ void __launch_bounds__(128, 2)
qgemm(const float* __restrict__ x, float* __restrict__ out) {
    extern __shared__ __half smB[];
    const uint32_t smb = smem_u32(smB);
    const int tid  = threadIdx.x;
    const int wid  = tid >> 5;
    const int lane = tid & 31;
    const int quad = lane & 3;       // t%4
    const int qrow = lane >> 2;      // t/4

    int myStart, myCount;
    if (blockIdx.x < NHI) { myStart = blockIdx.x * CHUNK_HI; myCount = CHUNK_HI; }
    else {
        myStart = NHI * CHUNK_HI + (blockIdx.x - NHI) * (CHUNK_HI - 1);
        myCount = CHUNK_HI - 1;
    }

    const int lgrp = lane >> 3, lrow = lane & 7;
    const uint32_t lbase = smb +
        (uint32_t)((((lgrp & 2) ? 64 : 0) + lrow) * BROW + (lgrp & 1) * 8) * 2;

    uint32_t A2[4][16][2];
    int last_t = -1;
    bool synced = false;

    for (int u = myStart; u < myStart + myCount; u++) {
        const int t = u >> 2, q = u & 3;
        const int base = (t * 4 + wid) * 32;

        // ---- (re)build A fragments when the tile changes.
        // Quad-mates (lane&~3) need the SAME 4 rows; each thread computes
        // sincos for only row rs=quad, then shares via quad shuffles (MUFU/4).
        if (t != last_t) {
            last_t = t;
            float sc[8], cc[8];
            {
                const int myrow = base + qrow + quad * 8;
                const float4* xp = (const float4*)(x + (size_t)myrow * 8);
                float4 x0 = xp[0], x1 = xp[1];
                float xv[8] = {x0.x, x0.y, x0.z, x0.w, x1.x, x1.y, x1.z, x1.w};
#pragma unroll
                for (int qq = 0; qq < 8; qq++)
                    __sincosf(0.5f * xv[qq], &sc[qq], &cc[qq]);
            }
#pragma unroll
            for (int rs = 0; rs < 4; rs++) {
                const int src = (lane & ~3) | rs;
                float c_[8], s_[8];
#pragma unroll
                for (int qq = 0; qq < 8; qq++) {
                    c_[qq] = __shfl_sync(FULL, cc[qq], src);
                    s_[qq] = __shfl_sync(FULL, sc[qq], src);
                }
                float hi16[16];
#pragma unroll
                for (int h = 0; h < 16; h++)
                    hi16[h] = ((h & 8) ? s_[0] : c_[0]) * ((h & 4) ? s_[1] : c_[1]) *
                              ((h & 2) ? s_[2] : c_[2]) * ((h & 1) ? s_[3] : c_[3]);
                float q5 = (quad & 2) ? s_[5] : c_[5];
                float q6 = (quad & 1) ? s_[6] : c_[6];
                float m56 = q5 * q6;
                float l00 = c_[4] * m56 * c_[7], l01 = c_[4] * m56 * s_[7];
                float l10 = s_[4] * m56 * c_[7], l11 = s_[4] * m56 * s_[7];
#pragma unroll
                for (int kk = 0; kk < 16; kk++) {
                    float h = hi16[kk];
                    __half2 plo = __floats2half2_rn(h * l00, h * l01);
                    __half2 phi = __floats2half2_rn(h * l10, h * l11);
                    A2[rs][kk][0] = *(uint32_t*)&plo;
                    A2[rs][kk][1] = *(uint32_t*)&phi;
                }
            }
        }

        // wait for build_u completion before first U read (overlaps A build above)
        if (!synced) { cudaGridDependencySynchronize(); synced = true; }

        // ---- B quarter q: smem rows 0-63 = Ure[n0..], 64-127 = Uim[n0..]
        const int n0 = q * 64;
#pragma unroll
        for (int j = 0; j < 32; j++) {
            int c = j * 128 + tid;
            int row = c >> 5, kc = (c & 31) * 8;
            const __half* src = (row < 64) ? (g_Ure + (size_t)(n0 + row) * 256 + kc)
                                           : (g_Uim + (size_t)(n0 + row - 64) * 256 + kc);
            *(uint4*)(smB + row * BROW + kc) = *(const uint4*)src;
        }
        __syncthreads();

        // ---- mainloop over the 8 n-tiles of this quarter
        float z7a[4] = {0,0,0,0}, z4a[4] = {0,0,0,0}, z3a[4] = {0,0,0,0},
              z2a[4] = {0,0,0,0}, Sc[4] = {0,0,0,0};
#pragma unroll
        for (int nt = 0; nt < 8; nt++) {
            float cre_e[8] = {0,0,0,0,0,0,0,0}, cim_e[8] = {0,0,0,0,0,0,0,0};
            float cre_o[8] = {0,0,0,0,0,0,0,0}, cim_o[8] = {0,0,0,0,0,0,0,0};
            uint32_t bufA[4], bufB[4];
            ldsm_x4(bufA[0], bufA[1], bufA[2], bufA[3],
                    lbase + (uint32_t)(nt * 8 * BROW) * 2);
#pragma unroll
            for (int kk = 0; kk < 16; kk++) {
                uint32_t* cur = (kk & 1) ? bufB : bufA;
                uint32_t* nxt = (kk & 1) ? bufA : bufB;
                if (kk < 15)
                    ldsm_x4(nxt[0], nxt[1], nxt[2], nxt[3],
                            lbase + (uint32_t)(nt * 8 * BROW + (kk + 1) * 16) * 2);
                float* cr = (kk & 1) ? cre_o : cre_e;
                float* ci = (kk & 1) ? cim_o : cim_e;
                mma16816(cr[0], cr[1], cr[2], cr[3],
                         A2[0][kk][0], A2[1][kk][0], A2[0][kk][1], A2[1][kk][1],
                         cur[0], cur[1]);
                mma16816(cr[4], cr[5], cr[6], cr[7],
                         A2[2][kk][0], A2[3][kk][0], A2[2][kk][1], A2[3][kk][1],
                         cur[0], cur[1]);
                mma16816(ci[0], ci[1], ci[2], ci[3],
                         A2[0][kk][0], A2[1][kk][0], A2[0][kk][1], A2[1][kk][1],
                         cur[2], cur[3]);
                mma16816(ci[4], ci[5], ci[6], ci[7],
                         A2[2][kk][0], A2[3][kk][0], A2[2][kk][1], A2[3][kk][1],
                         cur[2], cur[3]);
            }
#pragma unroll
            for (int rs = 0; rs < 4; rs++) {
                float r0 = cre_e[2*rs]   + cre_o[2*rs];
                float r1 = cre_e[2*rs+1] + cre_o[2*rs+1];
                float i0 = cim_e[2*rs]   + cim_o[2*rs];
                float i1 = cim_e[2*rs+1] + cim_o[2*rs+1];
                float p0 = r0 * r0 + i0 * i0;
                float p1 = r1 * r1 + i1 * i1;
                float d = p0 - p1, s = p0 + p1;
                z7a[rs] += d;
                Sc[rs] += s;
                z4a[rs] += (nt & 1) ? -s : s;
                z3a[rs] += (nt & 2) ? -s : s;
                z2a[rs] += (nt & 4) ? -s : s;
            }
        }

        // ---- per-unit epilogue (R12 best-total): butterfly + atomicAdd
#pragma unroll
        for (int rs = 0; rs < 4; rs++) {
            float z[8];
            z[0] = (q & 2) ? -Sc[rs] : Sc[rs];
            z[1] = (q & 1) ? -Sc[rs] : Sc[rs];
            z[2] = z2a[rs]; z[3] = z3a[rs]; z[4] = z4a[rs];
            z[5] = ((quad >> 1) & 1) ? -Sc[rs] : Sc[rs];
            z[6] = (quad & 1) ? -Sc[rs] : Sc[rs];
            z[7] = z7a[rs];
#pragma unroll
            for (int j = 0; j < 8; j++) {
                z[j] += __shfl_xor_sync(FULL, z[j], 1);
                z[j] += __shfl_xor_sync(FULL, z[j], 2);
            }
            const int row = base + qrow + rs * 8;
            atomicAdd(out + (size_t)row * 8 + 2 * quad,     z[2 * quad]);
            atomicAdd(out + (size_t)row * 8 + 2 * quad + 1, z[2 * quad + 1]);
        }
        __syncthreads();   // before next unit overwrites smB
    }
}

// ===================== host launcher =====================
extern "C" void kernel_launch(void* const* d_in, const int* in_sizes, int n_in,
                              void* d_out, int out_size) {
    const float* x    = (const float*)d_in[0];
    const float* conv = (const float*)d_in[1];
    const float* pool = (const float*)d_in[2];
    float* out = (float*)d_out;

    // zero output (accumulated via atomics)
    cudaMemsetAsync(d_out, 0, (size_t)out_size * sizeof(float), 0);

    build_u<<<256, 32>>>(conv, pool);   // one CTA (one warp) per U column

    static bool attr_set = false;
    if (!attr_set) {
        cudaFuncSetAttribute(qgemm, cudaFuncAttributeMaxDynamicSharedMemorySize, SMEM_TOTAL);
        attr_set = true;
    }

    cudaLaunchConfig_t cfg = {};
    cfg.gridDim = dim3(NCTA, 1, 1);
    cfg.blockDim = dim3(128, 1, 1);
    cfg.dynamicSmemBytes = SMEM_TOTAL;
    cfg.stream = 0;
    cudaLaunchAttribute attrs[1];
    attrs[0].id = cudaLaunchAttributeProgrammaticStreamSerialization;
    attrs[0].val.programmaticStreamSerializationAllowed = 1;
    cfg.attrs = attrs;
    cfg.numAttrs = 1;
    cudaLaunchKernelEx(&cfg, qgemm, x, out);
}